// round 17
// baseline (speedup 1.0000x reference)
#include <cuda_runtime.h>
#include <cuda_fp16.h>
#include <stdint.h>

// ============================================================================
// FA2-style flash attention, fp16 inputs / fp32 accumulation, via
// ldmatrix + mma.sync.m16n8k16 (base sm_103 target: tcgen05 unavailable).
//
// Kernels:
//  0) zero_flag / scan_mask: set g_mask_on = (mask has any nonzero), each run.
//  1) convert_kernel: Q/K/V fp32 -> fp16 pre-swizzled 8KB tile images
//     (Q pre-scaled by 0.125*log2(e)).
//  2) sdpa_hmma_kernel: 3-stage cp.async pipeline, log2-domain softmax,
//     uniform-branch mask application (skipped when mask is all zeros).
// ============================================================================

static constexpr int Hn = 16, Sn = 4096, Dn = 64;
static constexpr int BQ = 64, BK = 64;
static constexpr int NT = Sn / BK;           // 64 key tiles
static constexpr int TILE_ELEMS = 64 * 64;   // 4096 fp16 = 8KB

__device__ __half QT_g[Hn * NT * TILE_ELEMS];
__device__ __half KT_g[Hn * NT * TILE_ELEMS];
__device__ __half VT_g[Hn * NT * TILE_ELEMS];
__device__ int    g_mask_on;

// dynamic smem layout: Q staging doubles as V slot 2 after prologue
static constexpr int Q_OFF = 0;                    // 8KB (later: V slot 2)
static constexpr int K_OFF = 8192;                 // 3 x 8KB K slots
static constexpr int V_OFF = K_OFF + 3 * 8192;     // 2 x 8KB V slots (0,1)
static constexpr int SMEM_TOTAL = V_OFF + 2 * 8192;  // 49152 B

__device__ __forceinline__ uint32_t smem_u32(const void* p) {
    uint32_t a;
    asm("{ .reg .u64 t; cvta.to.shared.u64 t, %1; cvt.u32.u64 %0, t; }" : "=r"(a) : "l"(p));
    return a;
}
__device__ __forceinline__ float ex2f(float x) {
    float r;
    asm("ex2.approx.ftz.f32 %0, %1;" : "=f"(r) : "f"(x));
    return r;
}
__device__ __forceinline__ void ldsm4(uint32_t r[4], uint32_t addr) {
    asm volatile("ldmatrix.sync.aligned.m8n8.x4.shared.b16 {%0,%1,%2,%3}, [%4];"
                 : "=r"(r[0]), "=r"(r[1]), "=r"(r[2]), "=r"(r[3]) : "r"(addr));
}
__device__ __forceinline__ void ldsm4t(uint32_t r[4], uint32_t addr) {
    asm volatile("ldmatrix.sync.aligned.m8n8.x4.trans.shared.b16 {%0,%1,%2,%3}, [%4];"
                 : "=r"(r[0]), "=r"(r[1]), "=r"(r[2]), "=r"(r[3]) : "r"(addr));
}
__device__ __forceinline__ void mma16816(float c[4], const uint32_t a[4],
                                         uint32_t b0, uint32_t b1) {
    asm volatile(
        "mma.sync.aligned.m16n8k16.row.col.f32.f16.f16.f32 "
        "{%0,%1,%2,%3}, {%4,%5,%6,%7}, {%8,%9}, {%0,%1,%2,%3};"
        : "+f"(c[0]), "+f"(c[1]), "+f"(c[2]), "+f"(c[3])
        : "r"(a[0]), "r"(a[1]), "r"(a[2]), "r"(a[3]), "r"(b0), "r"(b1));
}
__device__ __forceinline__ void cpa16(uint32_t sdst, const void* gsrc) {
    asm volatile("cp.async.cg.shared.global [%0], [%1], 16;" :: "r"(sdst), "l"(gsrc));
}
#define CP_COMMIT() asm volatile("cp.async.commit_group;" ::: "memory")
#define CP_WAIT(n)  asm volatile("cp.async.wait_group %0;" :: "n"(n) : "memory")

// one 8KB tile: 128 threads x 4 x 16B
__device__ __forceinline__ void cpa_tile(uint32_t sdst, const char* gsrc, int tid) {
    #pragma unroll
    for (int it = 0; it < 4; ++it)
        cpa16(sdst + tid * 16 + it * 2048, gsrc + tid * 16 + it * 2048);
}

// ---------------------------------------------------------------------------
__global__ void zero_flag_kernel() { g_mask_on = 0; }

__global__ void __launch_bounds__(256)
scan_mask_kernel(const float4* __restrict__ M4, int n4) {
    bool nz = false;
    for (int i = blockIdx.x * blockDim.x + threadIdx.x; i < n4;
         i += gridDim.x * blockDim.x) {
        const float4 v = M4[i];
        nz |= (v.x != 0.0f) | (v.y != 0.0f) | (v.z != 0.0f) | (v.w != 0.0f);
    }
    if (__ballot_sync(0xffffffffu, nz)) {
        if ((threadIdx.x & 31) == 0) atomicOr(&g_mask_on, 1);
    }
}

// ---------------------------------------------------------------------------
// convert kernel: fp32 [64 x 64] block -> fp16 swizzled 8KB tile image.
// grid = (NT, Hn, 3). which: 0=Q (scaled), 1=K, 2=V.
// ---------------------------------------------------------------------------
__global__ void __launch_bounds__(128)
convert_kernel(const float* __restrict__ Q,
               const float* __restrict__ K,
               const float* __restrict__ V)
{
    constexpr float LOG2E = 1.4426950408889634f;
    const int tile = blockIdx.x, h = blockIdx.y, which = blockIdx.z;
    const int tid = threadIdx.x;

    const float* src = (which == 0 ? Q : which == 1 ? K : V)
                     + ((size_t)h * Sn + (size_t)tile * 64) * Dn;
    __half* dsth = (which == 0 ? QT_g : which == 1 ? KT_g : VT_g)
                 + (size_t)(h * NT + tile) * TILE_ELEMS;
    char* dst = reinterpret_cast<char*>(dsth);
    const float scale = (which == 0) ? 0.125f * LOG2E : 1.0f;

    #pragma unroll
    for (int it = 0; it < 8; ++it) {
        const int i = tid + it * 128;
        const int row = i >> 4, g = i & 15;
        float4 f = *reinterpret_cast<const float4*>(src + row * Dn + g * 4);
        __half2 h0 = __floats2half2_rn(f.x * scale, f.y * scale);
        __half2 h1 = __floats2half2_rn(f.z * scale, f.w * scale);
        const uint32_t byte = row * 128 + ((((g >> 1) ^ (row & 7)) << 4) | ((g & 1) << 3));
        *reinterpret_cast<__half2*>(dst + byte)     = h0;
        *reinterpret_cast<__half2*>(dst + byte + 4) = h1;
    }
}

// ---------------------------------------------------------------------------
// main attention kernel
// ---------------------------------------------------------------------------
__global__ void __launch_bounds__(128, 4)
sdpa_hmma_kernel(const float* __restrict__ M, float* __restrict__ O)
{
    extern __shared__ char smem[];
    const uint32_t sb = smem_u32(smem);

    const int tid = threadIdx.x;
    const int wid = tid >> 5;
    const int lid = tid & 31;
    const int g   = lid >> 2;
    const int t   = lid & 3;

    const int h   = blockIdx.x;   // heads adjacent: mask rows shared in L2
    const int qt  = blockIdx.y;
    const int q0  = qt * BQ;
    const int wq0 = wid * 16;

    constexpr float LOG2E = 1.4426950408889634f;
    const int mask_on = g_mask_on;   // uniform across grid

    const char* Qg = reinterpret_cast<const char*>(QT_g + (size_t)(h * NT + qt) * TILE_ELEMS);
    const char* Kg = reinterpret_cast<const char*>(KT_g + (size_t)h * NT * TILE_ELEMS);
    const char* Vg = reinterpret_cast<const char*>(VT_g + (size_t)h * NT * TILE_ELEMS);

    // ---- prologue: group0 = {Q, K0, V0}, group1 = {K1, V1} ----
    cpa_tile(sb + Q_OFF, Qg, tid);
    cpa_tile(sb + K_OFF, Kg, tid);
    cpa_tile(sb + V_OFF, Vg, tid);
    CP_COMMIT();
    cpa_tile(sb + K_OFF + 8192, Kg + 8192, tid);
    cpa_tile(sb + V_OFF + 8192, Vg + 8192, tid);
    CP_COMMIT();
    CP_WAIT(1);            // Q, K0, V0 landed
    __syncthreads();

    // ---- preload Q A-fragments (then Q region becomes V slot 2) ----
    uint32_t qa[4][4];
    {
        const int sel = lid >> 3;
        const int row = wq0 + (lid & 7) + ((sel & 1) << 3);
        #pragma unroll
        for (int ks = 0; ks < 4; ++ks) {
            const int chunk = 2 * ks + (sel >> 1);
            ldsm4(qa[ks], sb + Q_OFF + row * 128 + ((chunk ^ (row & 7)) << 4));
        }
    }
    __syncthreads();       // all warps read Q before V2 prefetch overwrites it

    float m0 = -1e30f, m1 = -1e30f, l0 = 0.0f, l1 = 0.0f;
    float oa[8][4];
    #pragma unroll
    for (int j = 0; j < 8; ++j)
        #pragma unroll
        for (int k = 0; k < 4; ++k) oa[j][k] = 0.0f;

    const float* mrow0 = M + (size_t)(q0 + wq0 + g) * Sn + 2 * t;
    const float* mrow1 = M + (size_t)(q0 + wq0 + g + 8) * Sn + 2 * t;

    for (int kt = 0; kt < NT; ++kt) {
        const int slot = kt % 3;
        const uint32_t kbase = sb + K_OFF + slot * 8192;
        const uint32_t vbase = sb + ((slot == 2) ? Q_OFF : V_OFF + slot * 8192);

        // ---- prefetch tile kt+2 into slot (kt+2)%3 ----
        const bool issued = (kt + 2 < NT);
        if (issued) {
            const int ps = (kt + 2) % 3;
            cpa_tile(sb + K_OFF + ps * 8192, Kg + (size_t)(kt + 2) * 8192, tid);
            cpa_tile(sb + ((ps == 2) ? Q_OFF : V_OFF + ps * 8192),
                     Vg + (size_t)(kt + 2) * 8192, tid);
            CP_COMMIT();
        }

        // ---- S(log2) = Q K^T ----
        float sc[8][4];
        #pragma unroll
        for (int j = 0; j < 8; ++j)
            #pragma unroll
            for (int k = 0; k < 4; ++k) sc[j][k] = 0.0f;

        {
            const int sel = lid >> 3;
            const int rlo = (lid & 7) + ((sel >> 1) << 3);
            #pragma unroll
            for (int ks = 0; ks < 4; ++ks) {
                const int chunk = 2 * ks + (sel & 1);
                #pragma unroll
                for (int j = 0; j < 4; ++j) {
                    const int row = 16 * j + rlo;
                    uint32_t kb[4];
                    ldsm4(kb, kbase + row * 128 + ((chunk ^ (row & 7)) << 4));
                    mma16816(sc[2 * j],     qa[ks], kb[0], kb[1]);
                    mma16816(sc[2 * j + 1], qa[ks], kb[2], kb[3]);
                }
            }
        }

        // ---- mask (only when mask has nonzero content; uniform branch) ----
        if (mask_on) {
            const float* mp0 = mrow0 + kt * BK;
            const float* mp1 = mrow1 + kt * BK;
            #pragma unroll
            for (int j = 0; j < 8; ++j) {
                const float2 v0 = __ldg(reinterpret_cast<const float2*>(mp0 + 8 * j));
                const float2 v1 = __ldg(reinterpret_cast<const float2*>(mp1 + 8 * j));
                sc[j][0] = fmaf(v0.x, LOG2E, sc[j][0]);
                sc[j][1] = fmaf(v0.y, LOG2E, sc[j][1]);
                sc[j][2] = fmaf(v1.x, LOG2E, sc[j][2]);
                sc[j][3] = fmaf(v1.y, LOG2E, sc[j][3]);
            }
        }

        // ---- online softmax (max over quad; l stays lane-partial) ----
        float rmax0 = sc[0][0], rmax1 = sc[0][2];
        #pragma unroll
        for (int j = 0; j < 8; ++j) {
            rmax0 = fmaxf(rmax0, fmaxf(sc[j][0], sc[j][1]));
            rmax1 = fmaxf(rmax1, fmaxf(sc[j][2], sc[j][3]));
        }
        #pragma unroll
        for (int sh = 1; sh < 4; sh <<= 1) {
            rmax0 = fmaxf(rmax0, __shfl_xor_sync(0xffffffffu, rmax0, sh));
            rmax1 = fmaxf(rmax1, __shfl_xor_sync(0xffffffffu, rmax1, sh));
        }
        const float mn0 = fmaxf(m0, rmax0), mn1 = fmaxf(m1, rmax1);
        const float a0 = ex2f(m0 - mn0), a1 = ex2f(m1 - mn1);
        m0 = mn0; m1 = mn1;

        float ps0 = 0.0f, ps1 = 0.0f;
        #pragma unroll
        for (int j = 0; j < 8; ++j) {
            sc[j][0] = ex2f(sc[j][0] - mn0); ps0 += sc[j][0];
            sc[j][1] = ex2f(sc[j][1] - mn0); ps0 += sc[j][1];
            sc[j][2] = ex2f(sc[j][2] - mn1); ps1 += sc[j][2];
            sc[j][3] = ex2f(sc[j][3] - mn1); ps1 += sc[j][3];
        }
        l0 = l0 * a0 + ps0;
        l1 = l1 * a1 + ps1;
        #pragma unroll
        for (int j = 0; j < 8; ++j) {
            oa[j][0] *= a0; oa[j][1] *= a0;
            oa[j][2] *= a1; oa[j][3] *= a1;
        }

        // ---- O += P V ----
        {
            const int sel = lid >> 3;
            const int rlo = (lid & 7) + ((sel & 1) << 3);
            #pragma unroll
            for (int j2 = 0; j2 < 4; ++j2) {
                uint32_t pa[4];
                {
                    __half2 hh;
                    hh = __floats2half2_rn(sc[2 * j2][0],     sc[2 * j2][1]);
                    pa[0] = *reinterpret_cast<uint32_t*>(&hh);
                    hh = __floats2half2_rn(sc[2 * j2][2],     sc[2 * j2][3]);
                    pa[1] = *reinterpret_cast<uint32_t*>(&hh);
                    hh = __floats2half2_rn(sc[2 * j2 + 1][0], sc[2 * j2 + 1][1]);
                    pa[2] = *reinterpret_cast<uint32_t*>(&hh);
                    hh = __floats2half2_rn(sc[2 * j2 + 1][2], sc[2 * j2 + 1][3]);
                    pa[3] = *reinterpret_cast<uint32_t*>(&hh);
                }
                const int row = 16 * j2 + rlo;
                #pragma unroll
                for (int dp = 0; dp < 4; ++dp) {
                    const int chunk = 2 * dp + (sel >> 1);
                    uint32_t vb[4];
                    ldsm4t(vb, vbase + row * 128 + ((chunk ^ (row & 7)) << 4));
                    mma16816(oa[2 * dp],     pa, vb[0], vb[1]);
                    mma16816(oa[2 * dp + 1], pa, vb[2], vb[3]);
                }
            }
        }

        // ---- pipeline wait: tile kt+1 must be resident before next iter ----
        if (issued) { CP_WAIT(1); } else { CP_WAIT(0); }
        __syncthreads();
    }

    // ---- epilogue: reduce l over quad, normalize, store fp32 ----
    #pragma unroll
    for (int sh = 1; sh < 4; sh <<= 1) {
        l0 += __shfl_xor_sync(0xffffffffu, l0, sh);
        l1 += __shfl_xor_sync(0xffffffffu, l1, sh);
    }
    const float i0 = 1.0f / l0, i1 = 1.0f / l1;
    float* or0 = O + (size_t)(h * Sn + q0 + wq0 + g) * Dn + 2 * t;
    float* or1 = or0 + 8 * Dn;
    #pragma unroll
    for (int j = 0; j < 8; ++j) {
        float2 v0 = make_float2(oa[j][0] * i0, oa[j][1] * i0);
        float2 v1 = make_float2(oa[j][2] * i1, oa[j][3] * i1);
        *reinterpret_cast<float2*>(or0 + 8 * j) = v0;
        *reinterpret_cast<float2*>(or1 + 8 * j) = v1;
    }
}

extern "C" void kernel_launch(void* const* d_in, const int* in_sizes, int n_in,
                              void* d_out, int out_size)
{
    (void)in_sizes; (void)n_in; (void)out_size;
    const float* Qp = (const float*)d_in[0];
    const float* Kp = (const float*)d_in[1];
    const float* Vp = (const float*)d_in[2];
    const float* Mp = (const float*)d_in[3];
    float* Op = (float*)d_out;

    zero_flag_kernel<<<1, 1>>>();
    scan_mask_kernel<<<2048, 256>>>(reinterpret_cast<const float4*>(Mp),
                                    Sn * Sn / 4);
    dim3 cgrid(NT, Hn, 3);
    convert_kernel<<<cgrid, 128>>>(Qp, Kp, Vp);

    cudaFuncSetAttribute(sdpa_hmma_kernel,
                         cudaFuncAttributeMaxDynamicSharedMemorySize, SMEM_TOTAL);
    dim3 grid(Hn, Sn / BQ);
    sdpa_hmma_kernel<<<grid, 128, SMEM_TOTAL>>>(Mp, Op);
}